// round 11
// baseline (speedup 1.0000x reference)
#include <cuda_runtime.h>
#include <cuda_bf16.h>
#include <cstdint>

// LSTM T=1024, B=64, D=512 — both phases HMMA (m16n8k16 bf16, 3-pass hi/lo).
// lstm_zx : Zx = x@Wi + b (parallel over t)  [unchanged from R10]
// lstm_rec: z = Zx + h@Wh; gates. R11: per-producer fine-grained flag polling
//           with predicated cp.async staging, st.release flag, zx prefetch.

#define TS   1024
#define NCTA 128
#define NTHR 512

// ---- zx smem layout (bytes) ----
#define ZW_HI   0
#define ZW_LO   66560
#define ZA_HI0  133120
#define ZA_LO0  151552
#define ZA_HI1  169984
#define ZA_LO1  188416
#define ZBIAS   206848
#define ZX_SMEM 207104

// ---- rec smem layout (bytes) ----
#define RW_HI   0
#define RW_LO   66560
#define RA_HI   133120
#define RA_LO   149760
#define RRED    166400
#define REC_SMEM 183808

__device__ float g_zx[(size_t)TS * NCTA * 1024];   // [t][cta][eb][dloc][gate]
__device__ __nv_bfloat16 g_hb[2][2][64 * 512];     // [buf][hi/lo][b][d]
__device__ unsigned g_count = 0;
__device__ volatile unsigned g_gen = 0;
__device__ unsigned g_flags[NCTA * 8];

// ===================== helpers =====================
__device__ __forceinline__ float sigf(float x) {
    return __fdividef(1.0f, 1.0f + __expf(-x));
}
__device__ __forceinline__ float tanhfast(float x) {
    float e = __expf(-2.0f * x);
    return __fdividef(1.0f - e, 1.0f + e);
}
__device__ __forceinline__ unsigned ldflag(const unsigned* p) {
    unsigned v;
    asm volatile("ld.global.cg.u32 %0, [%1];" : "=r"(v) : "l"(p));
    return v;
}
__device__ __forceinline__ void stflag_release(unsigned* p, unsigned v) {
    asm volatile("st.release.gpu.global.u32 [%0], %1;" :: "l"(p), "r"(v)
                 : "memory");
}
__device__ __forceinline__ void cpa16(void* dst, const void* src) {
    unsigned s = (unsigned)__cvta_generic_to_shared(dst);
    asm volatile("cp.async.cg.shared.global [%0], [%1], 16;" :: "r"(s), "l"(src));
}
#define CPA_COMMIT() asm volatile("cp.async.commit_group;" ::: "memory")
#define CPA_WAIT0()  asm volatile("cp.async.wait_group 0;" ::: "memory")

__device__ __forceinline__ void ldm4(uint32_t* r, uint32_t addr) {
    asm volatile("ldmatrix.sync.aligned.m8n8.x4.shared.b16 {%0,%1,%2,%3}, [%4];"
                 : "=r"(r[0]), "=r"(r[1]), "=r"(r[2]), "=r"(r[3]) : "r"(addr));
}
__device__ __forceinline__ void mma16816(float* d, const uint32_t* a,
                                         const uint32_t* b) {
    asm("mma.sync.aligned.m16n8k16.row.col.f32.bf16.bf16.f32 "
        "{%0,%1,%2,%3}, {%4,%5,%6,%7}, {%8,%9}, {%0,%1,%2,%3};"
        : "+f"(d[0]), "+f"(d[1]), "+f"(d[2]), "+f"(d[3])
        : "r"(a[0]), "r"(a[1]), "r"(a[2]), "r"(a[3]), "r"(b[0]), "r"(b[1]));
}
__device__ __forceinline__ uint32_t pack_hi_lo(float a, float b, uint32_t& lo) {
    __nv_bfloat16 ha = __float2bfloat16(a), hb = __float2bfloat16(b);
    float la = a - __bfloat162float(ha);
    float lb = b - __bfloat162float(hb);
    __nv_bfloat162 l2 = __floats2bfloat162_rn(la, lb);
    lo = *(uint32_t*)&l2;
    __nv_bfloat162 h2;
    h2.x = ha; h2.y = hb;
    return *(uint32_t*)&h2;
}
__device__ __forceinline__ void st_b16(__nv_bfloat16* p, __nv_bfloat16 v) {
    unsigned short u = *(unsigned short*)&v;
    asm volatile("st.global.cg.b16 [%0], %1;" :: "l"(p), "h"(u));
}

__device__ __forceinline__ void fill_w_bf16(char* whi, char* wlo,
                                            const float* W, int d0) {
    for (int i = threadIdx.x; i < 64 * 512; i += NTHR) {
        int c = i >> 9, k = i & 511;
        int zc = ((c >> 4) << 9) + d0 + (c & 15);
        float w = W[(size_t)k * 2048 + zc];
        __nv_bfloat16 h = __float2bfloat16(w);
        __nv_bfloat16 l = __float2bfloat16(w - __bfloat162float(h));
        int off = c * 1040 + k * 2;
        *(__nv_bfloat16*)(whi + off) = h;
        *(__nv_bfloat16*)(wlo + off) = l;
    }
}

// ========================= PHASE 1: HMMA Zx (R10, unchanged) ================
extern "C" __global__ void __launch_bounds__(NTHR, 1)
lstm_zx(const float* __restrict__ x,
        const float* __restrict__ Wi,
        const float* __restrict__ bias) {
    extern __shared__ char sm[];
    const uint32_t smb = (uint32_t)__cvta_generic_to_shared(sm);
    float* sbias = (float*)(sm + ZBIAS);

    const int tid = threadIdx.x;
    const int bid = blockIdx.x;
    const int gd = bid & 31, gb = bid >> 5;
    const int d0 = gd * 16;
    const int wid = tid >> 5;
    const int L   = tid & 31;

    fill_w_bf16(sm + ZW_HI, sm + ZW_LO, Wi, d0);
    if (tid < 64)
        sbias[tid] = bias[(tid >> 4) * 512 + d0 + (tid & 15)];

    const int mr = (wid & 3) * 32;
    const int nb = (wid >> 2) * 16;

    const uint32_t amr = (uint32_t)((mr + (L & 15)) * 144 + (L >> 4) * 16);
    const uint32_t boff =
        (uint32_t)((nb + (L & 7) + ((L >> 4) & 1) * 8) * 1040 +
                   ((L >> 3) & 1) * 16);
    const uint32_t bhi_lane = smb + ZW_HI + boff;
    const uint32_t blo_lane = smb + ZW_LO + boff;

    const int r = tid >> 2;
    const int q = tid & 3;
    const float* xrow_p = x + (size_t)(r >> 4) * 32768 +
                          (size_t)(gb * 16 + (r & 15)) * 512 + q * 16;
    char* ahiB[2] = {sm + ZA_HI0, sm + ZA_HI1};
    char* aloB[2] = {sm + ZA_LO0, sm + ZA_LO1};
    const uint32_t ahiS[2] = {smb + ZA_HI0, smb + ZA_HI1};
    const uint32_t aloS[2] = {smb + ZA_LO0, smb + ZA_LO1};

    unsigned gen0 = 0;
    if (tid == 0) gen0 = g_gen;
    unsigned epoch = 0;
    __syncthreads();

    for (int nt = 0; nt < 128; ++nt) {
        const int t0 = nt * 8;
        const float* xt = xrow_p + (size_t)t0 * 32768;

        float acc[16];
#pragma unroll
        for (int i = 0; i < 16; ++i) acc[i] = 0.f;

        float4 f0 = *(const float4*)(xt + 0);
        float4 f1 = *(const float4*)(xt + 4);
        float4 f2 = *(const float4*)(xt + 8);
        float4 f3 = *(const float4*)(xt + 12);

        for (int kc = 0; kc < 8; ++kc) {
            {
                uint4 hu0, hu1, lu0, lu1;
                hu0.x = pack_hi_lo(f0.x, f0.y, lu0.x);
                hu0.y = pack_hi_lo(f0.z, f0.w, lu0.y);
                hu0.z = pack_hi_lo(f1.x, f1.y, lu0.z);
                hu0.w = pack_hi_lo(f1.z, f1.w, lu0.w);
                hu1.x = pack_hi_lo(f2.x, f2.y, lu1.x);
                hu1.y = pack_hi_lo(f2.z, f2.w, lu1.y);
                hu1.z = pack_hi_lo(f3.x, f3.y, lu1.z);
                hu1.w = pack_hi_lo(f3.z, f3.w, lu1.w);
                char* ah = ahiB[kc & 1] + r * 144 + q * 32;
                char* al = aloB[kc & 1] + r * 144 + q * 32;
                *(uint4*)(ah) = hu0;
                *(uint4*)(ah + 16) = hu1;
                *(uint4*)(al) = lu0;
                *(uint4*)(al + 16) = lu1;
            }
            __syncthreads();

            if (kc < 7) {
                const float* xn = xt + (kc + 1) * 64;
                f0 = *(const float4*)(xn + 0);
                f1 = *(const float4*)(xn + 4);
                f2 = *(const float4*)(xn + 8);
                f3 = *(const float4*)(xn + 12);
            }

            const uint32_t ah_s = ahiS[kc & 1];
            const uint32_t al_s = aloS[kc & 1];
            const uint32_t kbyte = (uint32_t)kc * 128;
#pragma unroll
            for (int ks = 0; ks < 4; ++ks) {
                const uint32_t ko = kbyte + ks * 32;
                uint32_t ah0[4], ah1[4], bh[4], bl[4], al0[4], al1[4];
                ldm4(ah0, ah_s + amr + ks * 32);
                ldm4(ah1, ah_s + amr + 2304 + ks * 32);
                ldm4(bh, bhi_lane + ko);
                mma16816(acc + 0,  ah0, bh + 0);
                mma16816(acc + 4,  ah0, bh + 2);
                mma16816(acc + 8,  ah1, bh + 0);
                mma16816(acc + 12, ah1, bh + 2);
                ldm4(bl, blo_lane + ko);
                mma16816(acc + 0,  ah0, bl + 0);
                mma16816(acc + 4,  ah0, bl + 2);
                mma16816(acc + 8,  ah1, bl + 0);
                mma16816(acc + 12, ah1, bl + 2);
                ldm4(al0, al_s + amr + ks * 32);
                ldm4(al1, al_s + amr + 2304 + ks * 32);
                mma16816(acc + 0,  al0, bh + 0);
                mma16816(acc + 4,  al0, bh + 2);
                mma16816(acc + 8,  al1, bh + 0);
                mma16816(acc + 12, al1, bh + 2);
            }
            __syncthreads();
        }

#pragma unroll
        for (int mi = 0; mi < 2; ++mi) {
#pragma unroll
            for (int ni = 0; ni < 2; ++ni) {
                const float* d = acc + mi * 8 + ni * 4;
                int col = nb + 8 * ni + (L & 3) * 2;
                float bv0 = sbias[col], bv1 = sbias[col + 1];
                int row0 = mr + 16 * mi + (L >> 2);
#pragma unroll
                for (int rr = 0; rr < 2; ++rr) {
                    int row = row0 + rr * 8;
                    float* zp = g_zx + (size_t)(t0 + (row >> 4)) * 131072 +
                                bid * 1024 + (row & 15) * 64;
                    zp[(col & 15) * 4 + (col >> 4)] = d[rr * 2 + 0] + bv0;
                    zp[((col + 1) & 15) * 4 + ((col + 1) >> 4)] =
                        d[rr * 2 + 1] + bv1;
                }
            }
        }

        if ((nt & 31) == 31) {
            __syncthreads();
            if (tid == 0) {
                unsigned a = atomicAdd(&g_count, 1u);
                if (((a + 1u) & (NCTA - 1u)) == 0u) g_gen = g_gen + 1u;
                ++epoch;
                while ((unsigned)(g_gen - gen0) < epoch) __nanosleep(64);
            }
            __syncthreads();
        }
    }
}

// ========================= PHASE 2: HMMA recurrence (R11) ===================
extern "C" __global__ void __launch_bounds__(NTHR, 1)
lstm_rec(const float* __restrict__ c0,
         const float* __restrict__ h0,
         const float* __restrict__ Wh,
         float* __restrict__ out,
         long long out_size) {
    extern __shared__ char sm[];
    const uint32_t smb = (uint32_t)__cvta_generic_to_shared(sm);
    float* red = (float*)(sm + RRED);
    __shared__ unsigned s_fbase;

    const int tid = threadIdx.x;
    const int bid = blockIdx.x;
    const int gd  = bid & 31, gb = bid >> 5;
    const int d0  = gd * 16;
    const int wid = tid >> 5;
    const int L   = tid & 31;

    if (tid == 0) s_fbase = ldflag(&g_flags[bid * 8]);
    fill_w_bf16(sm + RW_HI, sm + RW_LO, Wh, d0);

    const int nq = wid & 3;
    const int kq = wid >> 2;

    const uint32_t amr = (uint32_t)((L & 15) * 1040 + (L >> 4) * 16);
    const uint32_t boff =
        (uint32_t)((nq * 16 + (L & 7) + ((L >> 4) & 1) * 8) * 1040 +
                   ((L >> 3) & 1) * 16);
    const uint32_t a_hi = smb + RA_HI + amr + kq * 256;
    const uint32_t a_lo = smb + RA_LO + amr + kq * 256;
    const uint32_t b_hi = smb + RW_HI + boff + kq * 256;
    const uint32_t b_lo = smb + RW_LO + boff + kq * 256;

    const int eb   = tid >> 4;   // reducer roles (tid<256)
    const int dloc = tid & 15;

    // staging roles: thread (hr, hc) stages row hr, dims [16hc, 16hc+16)
    // -> producer CTA = gb*32 + hc (exactly one)
    const int hr = tid >> 5;
    const int hc = tid & 31;
    char* ah_st = sm + RA_HI + hr * 1040 + hc * 32;
    char* al_st = sm + RA_LO + hr * 1040 + hc * 32;
    const unsigned* myflag = &g_flags[(gb * 32 + hc) * 8];

    float c_reg = 0.f;
    if (tid < 256) c_reg = c0[(gb * 16 + eb) * 512 + d0 + dloc];
    __syncthreads();
    const unsigned fbase = s_fbase;

    const float* zx_base = g_zx + (size_t)bid * 1024;

    // preload zx[0]
    float4 zx = make_float4(0.f, 0.f, 0.f, 0.f);
    if (tid < 256) zx = __ldcg((const float4*)(zx_base + (size_t)tid * 4));

    for (int t = 0; t < TS; ++t) {
        // ---- stage h (bf16 hi/lo) into smem ----
        if (t == 0) {
            const float* hp = h0 + (size_t)(gb * 16 + hr) * 512 + hc * 16;
            float4 f0 = *(const float4*)(hp + 0);
            float4 f1 = *(const float4*)(hp + 4);
            float4 f2 = *(const float4*)(hp + 8);
            float4 f3 = *(const float4*)(hp + 12);
            uint4 hu0, hu1, lu0, lu1;
            hu0.x = pack_hi_lo(f0.x, f0.y, lu0.x);
            hu0.y = pack_hi_lo(f0.z, f0.w, lu0.y);
            hu0.z = pack_hi_lo(f1.x, f1.y, lu0.z);
            hu0.w = pack_hi_lo(f1.z, f1.w, lu0.w);
            hu1.x = pack_hi_lo(f2.x, f2.y, lu1.x);
            hu1.y = pack_hi_lo(f2.z, f2.w, lu1.y);
            hu1.z = pack_hi_lo(f3.x, f3.y, lu1.z);
            hu1.w = pack_hi_lo(f3.z, f3.w, lu1.w);
            *(uint4*)(ah_st) = hu0;
            *(uint4*)(ah_st + 16) = hu1;
            *(uint4*)(al_st) = lu0;
            *(uint4*)(al_st + 16) = lu1;
        } else {
            // fine-grained: each lane waits on ITS producer only, fires
            // cp.async immediately (straggler wait overlaps staging).
            const unsigned tgt = fbase + (unsigned)t;
            const char* ghi = (const char*)(g_hb[t & 1][0] +
                              (size_t)(gb * 16 + hr) * 512) + hc * 32;
            const char* glo = (const char*)(g_hb[t & 1][1] +
                              (size_t)(gb * 16 + hr) * 512) + hc * 32;
            bool done = false;
            while (true) {
                if (!done && (int)(ldflag(myflag) - tgt) >= 0) {
                    cpa16(ah_st,      ghi);
                    cpa16(ah_st + 16, ghi + 16);
                    cpa16(al_st,      glo);
                    cpa16(al_st + 16, glo + 16);
                    CPA_COMMIT();
                    done = true;
                }
                if (__all_sync(0xffffffffu, done)) break;
            }
            CPA_WAIT0();
        }
        __syncthreads();

        // prefetch zx[t+1] (lands during mma/gates; DRAM-resident)
        float4 zx_next = make_float4(0.f, 0.f, 0.f, 0.f);
        if (tid < 256 && t + 1 < TS)
            zx_next = __ldcg((const float4*)(zx_base +
                        (size_t)(t + 1) * (NCTA * 1024) + (size_t)tid * 4));

        // ---- mma: 8 k16 steps x (2 n8) x 3 passes ----
        float acc[8];
#pragma unroll
        for (int i = 0; i < 8; ++i) acc[i] = 0.f;
#pragma unroll
        for (int ks = 0; ks < 8; ++ks) {
            const uint32_t ko = (uint32_t)ks * 32;
            uint32_t ah[4], al[4], bh[4], bl[4];
            ldm4(ah, a_hi + ko);
            ldm4(bh, b_hi + ko);
            mma16816(acc + 0, ah, bh + 0);
            mma16816(acc + 4, ah, bh + 2);
            ldm4(bl, b_lo + ko);
            mma16816(acc + 0, ah, bl + 0);
            mma16816(acc + 4, ah, bl + 2);
            ldm4(al, a_lo + ko);
            mma16816(acc + 0, al, bh + 0);
            mma16816(acc + 4, al, bh + 2);
        }

        // ---- partials: red[kq][16 rows][68] ----
        {
            int c0i = nq * 16 + (L & 3) * 2;
            int row0 = L >> 2;
#pragma unroll
            for (int rr = 0; rr < 2; ++rr) {
                int row = row0 + rr * 8;
                float* rp = &red[(kq * 16 + row) * 68];
                *(float2*)(rp + c0i)     = make_float2(acc[rr * 2 + 0],
                                                       acc[rr * 2 + 1]);
                *(float2*)(rp + c0i + 8) = make_float2(acc[4 + rr * 2 + 0],
                                                       acc[4 + rr * 2 + 1]);
            }
        }
        __syncthreads();

        // ---- reduce + gates + state update ----
        float hh = 0.f, cc = 0.f;
        if (tid < 256) {
            float zi = zx.x, zf = zx.y, zg = zx.z, zo = zx.w;
#pragma unroll
            for (int k4 = 0; k4 < 4; ++k4) {
                const float* r = &red[(k4 * 16 + eb) * 68 + dloc];
                zi += r[0];
                zf += r[16];
                zg += r[32];
                zo += r[48];
            }
            cc = sigf(zf) * c_reg + sigf(zi) * tanhfast(zg);
            hh = sigf(zo) * tanhfast(cc);
            c_reg = cc;
            __nv_bfloat16 hhi = __float2bfloat16(hh);
            __nv_bfloat16 hlo = __float2bfloat16(hh - __bfloat162float(hhi));
            size_t hoff = (size_t)(gb * 16 + eb) * 512 + d0 + dloc;
            st_b16(&g_hb[(t + 1) & 1][0][hoff], hhi);
            st_b16(&g_hb[(t + 1) & 1][1][hoff], hlo);
        }
        __syncthreads();   // all h stores issued before release

        if (tid == 0)
            stflag_release(&g_flags[bid * 8], fbase + (unsigned)(t + 1));

        // off-critical-path writes
        if (tid < 256) {
            int d = d0 + dloc;
            int bgl = gb * 16 + eb;
            out[(size_t)t * 32768 + bgl * 512 + d] = hh;
            if (t == TS - 1 && out_size >= 33554432LL + 65536LL) {
                out[33554432 + bgl * 512 + d] = cc;
                out[33554432 + 32768 + bgl * 512 + d] = hh;
            }
        }
        zx = zx_next;
    }
}

extern "C" void kernel_launch(void* const* d_in, const int* in_sizes, int n_in,
                              void* d_out, int out_size) {
    const float* x  = (const float*)d_in[0];
    const float* c0 = (const float*)d_in[1];
    const float* h0 = (const float*)d_in[2];
    const float* Wi = (const float*)d_in[3];
    const float* Wh = (const float*)d_in[4];
    const float* b  = (const float*)d_in[5];

    cudaFuncSetAttribute(lstm_zx,
                         cudaFuncAttributeMaxDynamicSharedMemorySize, ZX_SMEM);
    cudaFuncSetAttribute(lstm_rec,
                         cudaFuncAttributeMaxDynamicSharedMemorySize, REC_SMEM);

    lstm_zx<<<NCTA, NTHR, ZX_SMEM>>>(x, Wi, b);
    lstm_rec<<<NCTA, NTHR, REC_SMEM>>>(c0, h0, Wh, (float*)d_out,
                                       (long long)out_size);
}

// round 14
// speedup vs baseline: 1.3337x; 1.3337x over previous
#include <cuda_runtime.h>
#include <cuda_bf16.h>
#include <cstdint>

// LSTM T=1024, B=64, D=512 — both phases HMMA (m16n8k16 bf16, 3-pass hi/lo).
// lstm_zx : Zx = x@Wi + b (parallel over t)  [R10, unchanged]
// lstm_rec: exact R10 + acquire-poll (with nanosleep backoff) + zx prefetch.

#define TS   1024
#define NCTA 128
#define NTHR 512

// ---- zx smem layout (bytes) ----
#define ZW_HI   0
#define ZW_LO   66560
#define ZA_HI0  133120
#define ZA_LO0  151552
#define ZA_HI1  169984
#define ZA_LO1  188416
#define ZBIAS   206848
#define ZX_SMEM 207104

// ---- rec smem layout (bytes) ----
#define RW_HI   0
#define RW_LO   66560
#define RA_HI   133120
#define RA_LO   149760
#define RRED    166400
#define REC_SMEM 183808

__device__ float g_zx[(size_t)TS * NCTA * 1024];   // [t][cta][eb][dloc][gate]
__device__ __nv_bfloat16 g_hb[2][2][64 * 512];     // [buf][hi/lo][b][d]
__device__ unsigned g_count = 0;
__device__ volatile unsigned g_gen = 0;
__device__ unsigned g_flags[NCTA * 8];

// ===================== helpers =====================
__device__ __forceinline__ float sigf(float x) {
    return __fdividef(1.0f, 1.0f + __expf(-x));
}
__device__ __forceinline__ float tanhfast(float x) {
    float e = __expf(-2.0f * x);
    return __fdividef(1.0f - e, 1.0f + e);
}
__device__ __forceinline__ unsigned ldflag(const unsigned* p) {
    unsigned v;
    asm volatile("ld.global.cg.u32 %0, [%1];" : "=r"(v) : "l"(p));
    return v;
}
__device__ __forceinline__ unsigned ldflag_acq(const unsigned* p) {
    unsigned v;
    asm volatile("ld.acquire.gpu.global.u32 %0, [%1];" : "=r"(v) : "l"(p)
                 : "memory");
    return v;
}
__device__ __forceinline__ void cpa16(void* dst, const void* src) {
    unsigned s = (unsigned)__cvta_generic_to_shared(dst);
    asm volatile("cp.async.cg.shared.global [%0], [%1], 16;" :: "r"(s), "l"(src));
}
#define CPA_COMMIT() asm volatile("cp.async.commit_group;" ::: "memory")
#define CPA_WAIT0()  asm volatile("cp.async.wait_group 0;" ::: "memory")

__device__ __forceinline__ void ldm4(uint32_t* r, uint32_t addr) {
    asm volatile("ldmatrix.sync.aligned.m8n8.x4.shared.b16 {%0,%1,%2,%3}, [%4];"
                 : "=r"(r[0]), "=r"(r[1]), "=r"(r[2]), "=r"(r[3]) : "r"(addr));
}
__device__ __forceinline__ void mma16816(float* d, const uint32_t* a,
                                         const uint32_t* b) {
    asm("mma.sync.aligned.m16n8k16.row.col.f32.bf16.bf16.f32 "
        "{%0,%1,%2,%3}, {%4,%5,%6,%7}, {%8,%9}, {%0,%1,%2,%3};"
        : "+f"(d[0]), "+f"(d[1]), "+f"(d[2]), "+f"(d[3])
        : "r"(a[0]), "r"(a[1]), "r"(a[2]), "r"(a[3]), "r"(b[0]), "r"(b[1]));
}
__device__ __forceinline__ uint32_t pack_hi_lo(float a, float b, uint32_t& lo) {
    __nv_bfloat16 ha = __float2bfloat16(a), hb = __float2bfloat16(b);
    float la = a - __bfloat162float(ha);
    float lb = b - __bfloat162float(hb);
    __nv_bfloat162 l2 = __floats2bfloat162_rn(la, lb);
    lo = *(uint32_t*)&l2;
    __nv_bfloat162 h2;
    h2.x = ha; h2.y = hb;
    return *(uint32_t*)&h2;
}
__device__ __forceinline__ void st_b16(__nv_bfloat16* p, __nv_bfloat16 v) {
    unsigned short u = *(unsigned short*)&v;
    asm volatile("st.global.cg.b16 [%0], %1;" :: "l"(p), "h"(u));
}

__device__ __forceinline__ void fill_w_bf16(char* whi, char* wlo,
                                            const float* W, int d0) {
    for (int i = threadIdx.x; i < 64 * 512; i += NTHR) {
        int c = i >> 9, k = i & 511;
        int zc = ((c >> 4) << 9) + d0 + (c & 15);
        float w = W[(size_t)k * 2048 + zc];
        __nv_bfloat16 h = __float2bfloat16(w);
        __nv_bfloat16 l = __float2bfloat16(w - __bfloat162float(h));
        int off = c * 1040 + k * 2;
        *(__nv_bfloat16*)(whi + off) = h;
        *(__nv_bfloat16*)(wlo + off) = l;
    }
}

// ========================= PHASE 1: HMMA Zx (R10, unchanged) ================
extern "C" __global__ void __launch_bounds__(NTHR, 1)
lstm_zx(const float* __restrict__ x,
        const float* __restrict__ Wi,
        const float* __restrict__ bias) {
    extern __shared__ char sm[];
    const uint32_t smb = (uint32_t)__cvta_generic_to_shared(sm);
    float* sbias = (float*)(sm + ZBIAS);

    const int tid = threadIdx.x;
    const int bid = blockIdx.x;
    const int gd = bid & 31, gb = bid >> 5;
    const int d0 = gd * 16;
    const int wid = tid >> 5;
    const int L   = tid & 31;

    fill_w_bf16(sm + ZW_HI, sm + ZW_LO, Wi, d0);
    if (tid < 64)
        sbias[tid] = bias[(tid >> 4) * 512 + d0 + (tid & 15)];

    const int mr = (wid & 3) * 32;
    const int nb = (wid >> 2) * 16;

    const uint32_t amr = (uint32_t)((mr + (L & 15)) * 144 + (L >> 4) * 16);
    const uint32_t boff =
        (uint32_t)((nb + (L & 7) + ((L >> 4) & 1) * 8) * 1040 +
                   ((L >> 3) & 1) * 16);
    const uint32_t bhi_lane = smb + ZW_HI + boff;
    const uint32_t blo_lane = smb + ZW_LO + boff;

    const int r = tid >> 2;
    const int q = tid & 3;
    const float* xrow_p = x + (size_t)(r >> 4) * 32768 +
                          (size_t)(gb * 16 + (r & 15)) * 512 + q * 16;
    char* ahiB[2] = {sm + ZA_HI0, sm + ZA_HI1};
    char* aloB[2] = {sm + ZA_LO0, sm + ZA_LO1};
    const uint32_t ahiS[2] = {smb + ZA_HI0, smb + ZA_HI1};
    const uint32_t aloS[2] = {smb + ZA_LO0, smb + ZA_LO1};

    unsigned gen0 = 0;
    if (tid == 0) gen0 = g_gen;
    unsigned epoch = 0;
    __syncthreads();

    for (int nt = 0; nt < 128; ++nt) {
        const int t0 = nt * 8;
        const float* xt = xrow_p + (size_t)t0 * 32768;

        float acc[16];
#pragma unroll
        for (int i = 0; i < 16; ++i) acc[i] = 0.f;

        float4 f0 = *(const float4*)(xt + 0);
        float4 f1 = *(const float4*)(xt + 4);
        float4 f2 = *(const float4*)(xt + 8);
        float4 f3 = *(const float4*)(xt + 12);

        for (int kc = 0; kc < 8; ++kc) {
            {
                uint4 hu0, hu1, lu0, lu1;
                hu0.x = pack_hi_lo(f0.x, f0.y, lu0.x);
                hu0.y = pack_hi_lo(f0.z, f0.w, lu0.y);
                hu0.z = pack_hi_lo(f1.x, f1.y, lu0.z);
                hu0.w = pack_hi_lo(f1.z, f1.w, lu0.w);
                hu1.x = pack_hi_lo(f2.x, f2.y, lu1.x);
                hu1.y = pack_hi_lo(f2.z, f2.w, lu1.y);
                hu1.z = pack_hi_lo(f3.x, f3.y, lu1.z);
                hu1.w = pack_hi_lo(f3.z, f3.w, lu1.w);
                char* ah = ahiB[kc & 1] + r * 144 + q * 32;
                char* al = aloB[kc & 1] + r * 144 + q * 32;
                *(uint4*)(ah) = hu0;
                *(uint4*)(ah + 16) = hu1;
                *(uint4*)(al) = lu0;
                *(uint4*)(al + 16) = lu1;
            }
            __syncthreads();

            if (kc < 7) {
                const float* xn = xt + (kc + 1) * 64;
                f0 = *(const float4*)(xn + 0);
                f1 = *(const float4*)(xn + 4);
                f2 = *(const float4*)(xn + 8);
                f3 = *(const float4*)(xn + 12);
            }

            const uint32_t ah_s = ahiS[kc & 1];
            const uint32_t al_s = aloS[kc & 1];
            const uint32_t kbyte = (uint32_t)kc * 128;
#pragma unroll
            for (int ks = 0; ks < 4; ++ks) {
                const uint32_t ko = kbyte + ks * 32;
                uint32_t ah0[4], ah1[4], bh[4], bl[4], al0[4], al1[4];
                ldm4(ah0, ah_s + amr + ks * 32);
                ldm4(ah1, ah_s + amr + 2304 + ks * 32);
                ldm4(bh, bhi_lane + ko);
                mma16816(acc + 0,  ah0, bh + 0);
                mma16816(acc + 4,  ah0, bh + 2);
                mma16816(acc + 8,  ah1, bh + 0);
                mma16816(acc + 12, ah1, bh + 2);
                ldm4(bl, blo_lane + ko);
                mma16816(acc + 0,  ah0, bl + 0);
                mma16816(acc + 4,  ah0, bl + 2);
                mma16816(acc + 8,  ah1, bl + 0);
                mma16816(acc + 12, ah1, bl + 2);
                ldm4(al0, al_s + amr + ks * 32);
                ldm4(al1, al_s + amr + 2304 + ks * 32);
                mma16816(acc + 0,  al0, bh + 0);
                mma16816(acc + 4,  al0, bh + 2);
                mma16816(acc + 8,  al1, bh + 0);
                mma16816(acc + 12, al1, bh + 2);
            }
            __syncthreads();
        }

#pragma unroll
        for (int mi = 0; mi < 2; ++mi) {
#pragma unroll
            for (int ni = 0; ni < 2; ++ni) {
                const float* d = acc + mi * 8 + ni * 4;
                int col = nb + 8 * ni + (L & 3) * 2;
                float bv0 = sbias[col], bv1 = sbias[col + 1];
                int row0 = mr + 16 * mi + (L >> 2);
#pragma unroll
                for (int rr = 0; rr < 2; ++rr) {
                    int row = row0 + rr * 8;
                    float* zp = g_zx + (size_t)(t0 + (row >> 4)) * 131072 +
                                bid * 1024 + (row & 15) * 64;
                    zp[(col & 15) * 4 + (col >> 4)] = d[rr * 2 + 0] + bv0;
                    zp[((col + 1) & 15) * 4 + ((col + 1) >> 4)] =
                        d[rr * 2 + 1] + bv1;
                }
            }
        }

        if ((nt & 31) == 31) {
            __syncthreads();
            if (tid == 0) {
                unsigned a = atomicAdd(&g_count, 1u);
                if (((a + 1u) & (NCTA - 1u)) == 0u) g_gen = g_gen + 1u;
                ++epoch;
                while ((unsigned)(g_gen - gen0) < epoch) __nanosleep(64);
            }
            __syncthreads();
        }
    }
}

// ========================= PHASE 2: HMMA recurrence (R14) ===================
extern "C" __global__ void __launch_bounds__(NTHR, 1)
lstm_rec(const float* __restrict__ c0,
         const float* __restrict__ h0,
         const float* __restrict__ Wh,
         float* __restrict__ out,
         long long out_size) {
    extern __shared__ char sm[];
    const uint32_t smb = (uint32_t)__cvta_generic_to_shared(sm);
    float* red = (float*)(sm + RRED);
    __shared__ unsigned s_fbase;

    const int tid = threadIdx.x;
    const int bid = blockIdx.x;
    const int gd  = bid & 31, gb = bid >> 5;
    const int d0  = gd * 16;
    const int wid = tid >> 5;
    const int L   = tid & 31;

    if (tid == 0) s_fbase = ldflag(&g_flags[bid * 8]);
    fill_w_bf16(sm + RW_HI, sm + RW_LO, Wh, d0);

    const int nq = wid & 3;
    const int kq = wid >> 2;

    const uint32_t amr = (uint32_t)((L & 15) * 1040 + (L >> 4) * 16);
    const uint32_t boff =
        (uint32_t)((nq * 16 + (L & 7) + ((L >> 4) & 1) * 8) * 1040 +
                   ((L >> 3) & 1) * 16);
    const uint32_t a_hi = smb + RA_HI + amr + kq * 256;
    const uint32_t a_lo = smb + RA_LO + amr + kq * 256;
    const uint32_t b_hi = smb + RW_HI + boff + kq * 256;
    const uint32_t b_lo = smb + RW_LO + boff + kq * 256;

    const int eb   = tid >> 4;   // reducer roles (tid<256)
    const int dloc = tid & 15;

    const int hr = tid >> 5;     // staging rows
    const int hc = tid & 31;

    float c_reg = 0.f;
    if (tid < 256) c_reg = c0[(gb * 16 + eb) * 512 + d0 + dloc];
    __syncthreads();
    const unsigned fbase = s_fbase;

    const float* zx_base = g_zx + (size_t)bid * 1024;

    // preload zx[0] (validated in passing R11)
    float4 zx = make_float4(0.f, 0.f, 0.f, 0.f);
    if (tid < 256) zx = __ldcg((const float4*)(zx_base + (size_t)tid * 4));

    for (int t = 0; t < TS; ++t) {
        // ---- group wait: 32 threads poll 32 producers (acquire + backoff) ----
        if (t > 0 && tid < 32) {
            unsigned tgt = fbase + (unsigned)t;
            const unsigned* fp = &g_flags[(gb * 32 + tid) * 8];
            while ((int)(ldflag_acq(fp) - tgt) < 0) __nanosleep(32);
        }
        __syncthreads();

        // ---- stage h (bf16 hi/lo) into smem ----
        if (t == 0) {
            const float* hp = h0 + (size_t)(gb * 16 + hr) * 512 + hc * 16;
            float4 f0 = *(const float4*)(hp + 0);
            float4 f1 = *(const float4*)(hp + 4);
            float4 f2 = *(const float4*)(hp + 8);
            float4 f3 = *(const float4*)(hp + 12);
            uint4 hu0, hu1, lu0, lu1;
            hu0.x = pack_hi_lo(f0.x, f0.y, lu0.x);
            hu0.y = pack_hi_lo(f0.z, f0.w, lu0.y);
            hu0.z = pack_hi_lo(f1.x, f1.y, lu0.z);
            hu0.w = pack_hi_lo(f1.z, f1.w, lu0.w);
            hu1.x = pack_hi_lo(f2.x, f2.y, lu1.x);
            hu1.y = pack_hi_lo(f2.z, f2.w, lu1.y);
            hu1.z = pack_hi_lo(f3.x, f3.y, lu1.z);
            hu1.w = pack_hi_lo(f3.z, f3.w, lu1.w);
            char* ah = sm + RA_HI + hr * 1040 + hc * 32;
            char* al = sm + RA_LO + hr * 1040 + hc * 32;
            *(uint4*)(ah) = hu0;
            *(uint4*)(ah + 16) = hu1;
            *(uint4*)(al) = lu0;
            *(uint4*)(al + 16) = lu1;
        } else {
            const __nv_bfloat16* hhi = g_hb[t & 1][0] +
                                       (size_t)(gb * 16 + hr) * 512;
            const __nv_bfloat16* hlo = g_hb[t & 1][1] +
                                       (size_t)(gb * 16 + hr) * 512;
            char* ah = sm + RA_HI + hr * 1040;
            char* al = sm + RA_LO + hr * 1040;
            cpa16(ah + hc * 16,        (const char*)hhi + hc * 16);
            cpa16(ah + (hc + 32) * 16, (const char*)hhi + (hc + 32) * 16);
            cpa16(al + hc * 16,        (const char*)hlo + hc * 16);
            cpa16(al + (hc + 32) * 16, (const char*)hlo + (hc + 32) * 16);
            CPA_COMMIT();
            CPA_WAIT0();
        }
        __syncthreads();

        // prefetch zx[t+1] (lands under mma/gates)
        float4 zx_next = make_float4(0.f, 0.f, 0.f, 0.f);
        if (tid < 256 && t + 1 < TS)
            zx_next = __ldcg((const float4*)(zx_base +
                        (size_t)(t + 1) * (NCTA * 1024) + (size_t)tid * 4));

        // ---- mma: 8 k16 steps x (2 n8) x 3 passes ----
        float acc[8];
#pragma unroll
        for (int i = 0; i < 8; ++i) acc[i] = 0.f;
#pragma unroll
        for (int ks = 0; ks < 8; ++ks) {
            const uint32_t ko = (uint32_t)ks * 32;
            uint32_t ah[4], al[4], bh[4], bl[4];
            ldm4(ah, a_hi + ko);
            ldm4(bh, b_hi + ko);
            mma16816(acc + 0, ah, bh + 0);
            mma16816(acc + 4, ah, bh + 2);
            ldm4(bl, b_lo + ko);
            mma16816(acc + 0, ah, bl + 0);
            mma16816(acc + 4, ah, bl + 2);
            ldm4(al, a_lo + ko);
            mma16816(acc + 0, al, bh + 0);
            mma16816(acc + 4, al, bh + 2);
        }

        // ---- partials: red[kq][16 rows][68] ----
        {
            int c0i = nq * 16 + (L & 3) * 2;
            int row0 = L >> 2;
#pragma unroll
            for (int rr = 0; rr < 2; ++rr) {
                int row = row0 + rr * 8;
                float* rp = &red[(kq * 16 + row) * 68];
                *(float2*)(rp + c0i)     = make_float2(acc[rr * 2 + 0],
                                                       acc[rr * 2 + 1]);
                *(float2*)(rp + c0i + 8) = make_float2(acc[4 + rr * 2 + 0],
                                                       acc[4 + rr * 2 + 1]);
            }
        }
        __syncthreads();

        // ---- reduce + gates + state update (R10 scalar publish) ----
        float hh = 0.f, cc = 0.f;
        if (tid < 256) {
            float zi = zx.x, zf = zx.y, zg = zx.z, zo = zx.w;
#pragma unroll
            for (int k4 = 0; k4 < 4; ++k4) {
                const float* r = &red[(k4 * 16 + eb) * 68 + dloc];
                zi += r[0];
                zf += r[16];
                zg += r[32];
                zo += r[48];
            }
            cc = sigf(zf) * c_reg + sigf(zi) * tanhfast(zg);
            hh = sigf(zo) * tanhfast(cc);
            c_reg = cc;
            __nv_bfloat16 hhi = __float2bfloat16(hh);
            __nv_bfloat16 hlo = __float2bfloat16(hh - __bfloat162float(hhi));
            size_t hoff = (size_t)(gb * 16 + eb) * 512 + d0 + dloc;
            st_b16(&g_hb[(t + 1) & 1][0][hoff], hhi);
            st_b16(&g_hb[(t + 1) & 1][1][hoff], hlo);
        }
        __syncthreads();   // all h stores issued before release

        if (tid == 0) {
            asm volatile("fence.acq_rel.gpu;" ::: "memory");
            __stcg(&g_flags[bid * 8], fbase + (unsigned)(t + 1));
        }

        // off-critical-path writes
        if (tid < 256) {
            int d = d0 + dloc;
            int bgl = gb * 16 + eb;
            out[(size_t)t * 32768 + bgl * 512 + d] = hh;
            if (t == TS - 1 && out_size >= 33554432LL + 65536LL) {
                out[33554432 + bgl * 512 + d] = cc;
                out[33554432 + 32768 + bgl * 512 + d] = hh;
            }
        }
        zx = zx_next;
    }
}

extern "C" void kernel_launch(void* const* d_in, const int* in_sizes, int n_in,
                              void* d_out, int out_size) {
    const float* x  = (const float*)d_in[0];
    const float* c0 = (const float*)d_in[1];
    const float* h0 = (const float*)d_in[2];
    const float* Wi = (const float*)d_in[3];
    const float* Wh = (const float*)d_in[4];
    const float* b  = (const float*)d_in[5];

    cudaFuncSetAttribute(lstm_zx,
                         cudaFuncAttributeMaxDynamicSharedMemorySize, ZX_SMEM);
    cudaFuncSetAttribute(lstm_rec,
                         cudaFuncAttributeMaxDynamicSharedMemorySize, REC_SMEM);

    lstm_zx<<<NCTA, NTHR, ZX_SMEM>>>(x, Wi, b);
    lstm_rec<<<NCTA, NTHR, REC_SMEM>>>(c0, h0, Wh, (float*)d_out,
                                       (long long)out_size);
}

// round 15
// speedup vs baseline: 1.4330x; 1.0744x over previous
#include <cuda_runtime.h>
#include <cuda_bf16.h>
#include <cstdint>

// LSTM T=1024, B=64, D=512 — both phases HMMA (m16n8k16 bf16, 3-pass hi/lo).
// lstm_cvt: x fp32 -> bf16 hi/lo planes (one-time, bandwidth-bound).
// lstm_zx : Zx = x@Wi + b; A tiles cp.async-staged from g_xb (no in-loop cvt).
// lstm_rec: recurrence, byte-identical to R14 (passing).

#define TS   1024
#define NCTA 128
#define NTHR 512

// ---- zx smem layout (bytes) ----
#define ZW_HI   0
#define ZW_LO   66560
#define ZA_HI0  133120
#define ZA_LO0  151552
#define ZA_HI1  169984
#define ZA_LO1  188416
#define ZBIAS   206848
#define ZX_SMEM 207104

// ---- rec smem layout (bytes) ----
#define RW_HI   0
#define RW_LO   66560
#define RA_HI   133120
#define RA_LO   149760
#define RRED    166400
#define REC_SMEM 183808

__device__ float g_zx[(size_t)TS * NCTA * 1024];      // [t][cta][eb][dloc][gate]
__device__ __nv_bfloat16 g_xb[2][(size_t)TS * 64 * 512];  // x hi/lo planes
__device__ __nv_bfloat16 g_hb[2][2][64 * 512];        // [buf][hi/lo][b][d]
__device__ unsigned g_count = 0;
__device__ volatile unsigned g_gen = 0;
__device__ unsigned g_flags[NCTA * 8];

// ===================== helpers =====================
__device__ __forceinline__ float sigf(float x) {
    return __fdividef(1.0f, 1.0f + __expf(-x));
}
__device__ __forceinline__ float tanhfast(float x) {
    float e = __expf(-2.0f * x);
    return __fdividef(1.0f - e, 1.0f + e);
}
__device__ __forceinline__ unsigned ldflag(const unsigned* p) {
    unsigned v;
    asm volatile("ld.global.cg.u32 %0, [%1];" : "=r"(v) : "l"(p));
    return v;
}
__device__ __forceinline__ unsigned ldflag_acq(const unsigned* p) {
    unsigned v;
    asm volatile("ld.acquire.gpu.global.u32 %0, [%1];" : "=r"(v) : "l"(p)
                 : "memory");
    return v;
}
__device__ __forceinline__ void cpa16(void* dst, const void* src) {
    unsigned s = (unsigned)__cvta_generic_to_shared(dst);
    asm volatile("cp.async.cg.shared.global [%0], [%1], 16;" :: "r"(s), "l"(src));
}
#define CPA_COMMIT() asm volatile("cp.async.commit_group;" ::: "memory")
#define CPA_WAIT1()  asm volatile("cp.async.wait_group 1;" ::: "memory")
#define CPA_WAIT0()  asm volatile("cp.async.wait_group 0;" ::: "memory")

__device__ __forceinline__ void ldm4(uint32_t* r, uint32_t addr) {
    asm volatile("ldmatrix.sync.aligned.m8n8.x4.shared.b16 {%0,%1,%2,%3}, [%4];"
                 : "=r"(r[0]), "=r"(r[1]), "=r"(r[2]), "=r"(r[3]) : "r"(addr));
}
__device__ __forceinline__ void mma16816(float* d, const uint32_t* a,
                                         const uint32_t* b) {
    asm("mma.sync.aligned.m16n8k16.row.col.f32.bf16.bf16.f32 "
        "{%0,%1,%2,%3}, {%4,%5,%6,%7}, {%8,%9}, {%0,%1,%2,%3};"
        : "+f"(d[0]), "+f"(d[1]), "+f"(d[2]), "+f"(d[3])
        : "r"(a[0]), "r"(a[1]), "r"(a[2]), "r"(a[3]), "r"(b[0]), "r"(b[1]));
}
__device__ __forceinline__ uint32_t pack_hi_lo(float a, float b, uint32_t& lo) {
    __nv_bfloat16 ha = __float2bfloat16(a), hb = __float2bfloat16(b);
    float la = a - __bfloat162float(ha);
    float lb = b - __bfloat162float(hb);
    __nv_bfloat162 l2 = __floats2bfloat162_rn(la, lb);
    lo = *(uint32_t*)&l2;
    __nv_bfloat162 h2;
    h2.x = ha; h2.y = hb;
    return *(uint32_t*)&h2;
}
__device__ __forceinline__ void st_b16(__nv_bfloat16* p, __nv_bfloat16 v) {
    unsigned short u = *(unsigned short*)&v;
    asm volatile("st.global.cg.b16 [%0], %1;" :: "l"(p), "h"(u));
}

__device__ __forceinline__ void fill_w_bf16(char* whi, char* wlo,
                                            const float* W, int d0) {
    for (int i = threadIdx.x; i < 64 * 512; i += NTHR) {
        int c = i >> 9, k = i & 511;
        int zc = ((c >> 4) << 9) + d0 + (c & 15);
        float w = W[(size_t)k * 2048 + zc];
        __nv_bfloat16 h = __float2bfloat16(w);
        __nv_bfloat16 l = __float2bfloat16(w - __bfloat162float(h));
        int off = c * 1040 + k * 2;
        *(__nv_bfloat16*)(whi + off) = h;
        *(__nv_bfloat16*)(wlo + off) = l;
    }
}

// ========================= PREPASS: x -> bf16 hi/lo =========================
extern "C" __global__ void __launch_bounds__(NTHR, 1)
lstm_cvt(const float* __restrict__ x) {
    const size_t n4 = (size_t)TS * 64 * 512 / 4;
    const float4* x4 = (const float4*)x;
    uint2* hb = (uint2*)g_xb[0];
    uint2* lb = (uint2*)g_xb[1];
    for (size_t i = (size_t)blockIdx.x * NTHR + threadIdx.x; i < n4;
         i += (size_t)NCTA * NTHR) {
        float4 f = x4[i];
        uint32_t l0, l1;
        uint32_t h0 = pack_hi_lo(f.x, f.y, l0);
        uint32_t h1 = pack_hi_lo(f.z, f.w, l1);
        hb[i] = make_uint2(h0, h1);
        lb[i] = make_uint2(l0, l1);
    }
}

// ========================= PHASE 1: HMMA Zx (R15) ===========================
extern "C" __global__ void __launch_bounds__(NTHR, 1)
lstm_zx(const float* __restrict__ Wi,
        const float* __restrict__ bias) {
    extern __shared__ char sm[];
    const uint32_t smb = (uint32_t)__cvta_generic_to_shared(sm);
    float* sbias = (float*)(sm + ZBIAS);

    const int tid = threadIdx.x;
    const int bid = blockIdx.x;
    const int gd = bid & 31, gb = bid >> 5;
    const int d0 = gd * 16;
    const int wid = tid >> 5;
    const int L   = tid & 31;

    fill_w_bf16(sm + ZW_HI, sm + ZW_LO, Wi, d0);
    if (tid < 64)
        sbias[tid] = bias[(tid >> 4) * 512 + d0 + (tid & 15)];

    const int mr = (wid & 3) * 32;
    const int nb = (wid >> 2) * 16;

    const uint32_t amr = (uint32_t)((mr + (L & 15)) * 144 + (L >> 4) * 16);
    const uint32_t boff =
        (uint32_t)((nb + (L & 7) + ((L >> 4) & 1) * 8) * 1040 +
                   ((L >> 3) & 1) * 16);
    const uint32_t bhi_lane = smb + ZW_HI + boff;
    const uint32_t blo_lane = smb + ZW_LO + boff;

    // staging roles: r = A row, q = 32B quarter of the 128B chunk row
    const int r = tid >> 2;
    const int q = tid & 3;
    char* ahiB[2] = {sm + ZA_HI0, sm + ZA_HI1};
    char* aloB[2] = {sm + ZA_LO0, sm + ZA_LO1};
    const uint32_t ahiS[2] = {smb + ZA_HI0, smb + ZA_HI1};
    const uint32_t aloS[2] = {smb + ZA_LO0, smb + ZA_LO1};
    char* ahd[2] = {ahiB[0] + r * 144 + q * 32, ahiB[1] + r * 144 + q * 32};
    char* ald[2] = {aloB[0] + r * 144 + q * 32, aloB[1] + r * 144 + q * 32};

    // global row base for this thread's A row (dims advance by chunk)
    const size_t rowelem = ((size_t)(r >> 4) * 64 + gb * 16 + (r & 15)) * 512;

    unsigned gen0 = 0;
    if (tid == 0) gen0 = g_gen;
    unsigned epoch = 0;
    __syncthreads();

    for (int nt = 0; nt < 128; ++nt) {
        const int t0 = nt * 8;
        const char* xh = (const char*)(g_xb[0] + rowelem +
                                       (size_t)t0 * 32768) + q * 32;
        const char* xl = (const char*)(g_xb[1] + rowelem +
                                       (size_t)t0 * 32768) + q * 32;

        float acc[16];
#pragma unroll
        for (int i = 0; i < 16; ++i) acc[i] = 0.f;

        // preload chunk 0 into buf0 (buf0 free: last read 2 chunks ago)
        cpa16(ahd[0], xh);
        cpa16(ahd[0] + 16, xh + 16);
        cpa16(ald[0], xl);
        cpa16(ald[0] + 16, xl + 16);
        CPA_COMMIT();

        for (int kc = 0; kc < 8; ++kc) {
            if (kc < 7) {
                const char* xhn = xh + (kc + 1) * 128;
                const char* xln = xl + (kc + 1) * 128;
                int nb2 = (kc + 1) & 1;
                cpa16(ahd[nb2], xhn);
                cpa16(ahd[nb2] + 16, xhn + 16);
                cpa16(ald[nb2], xln);
                cpa16(ald[nb2] + 16, xln + 16);
                CPA_COMMIT();
                CPA_WAIT1();
            } else {
                CPA_WAIT0();
            }
            __syncthreads();   // chunk kc staged by ALL threads; prior mma done

            const uint32_t ah_s = ahiS[kc & 1];
            const uint32_t al_s = aloS[kc & 1];
            const uint32_t kbyte = (uint32_t)kc * 128;
#pragma unroll
            for (int ks = 0; ks < 4; ++ks) {
                const uint32_t ko = kbyte + ks * 32;
                uint32_t ah0[4], ah1[4], bh[4], bl[4], al0[4], al1[4];
                ldm4(ah0, ah_s + amr + ks * 32);
                ldm4(ah1, ah_s + amr + 2304 + ks * 32);
                ldm4(bh, bhi_lane + ko);
                mma16816(acc + 0,  ah0, bh + 0);
                mma16816(acc + 4,  ah0, bh + 2);
                mma16816(acc + 8,  ah1, bh + 0);
                mma16816(acc + 12, ah1, bh + 2);
                ldm4(bl, blo_lane + ko);
                mma16816(acc + 0,  ah0, bl + 0);
                mma16816(acc + 4,  ah0, bl + 2);
                mma16816(acc + 8,  ah1, bl + 0);
                mma16816(acc + 12, ah1, bl + 2);
                ldm4(al0, al_s + amr + ks * 32);
                ldm4(al1, al_s + amr + 2304 + ks * 32);
                mma16816(acc + 0,  al0, bh + 0);
                mma16816(acc + 4,  al0, bh + 2);
                mma16816(acc + 8,  al1, bh + 0);
                mma16816(acc + 12, al1, bh + 2);
            }
            __syncthreads();   // mma reads done before buffer reuse
        }

        // epilogue: bias + scatter to g_zx layout [t][cta][eb][dloc][gate]
#pragma unroll
        for (int mi = 0; mi < 2; ++mi) {
#pragma unroll
            for (int ni = 0; ni < 2; ++ni) {
                const float* d = acc + mi * 8 + ni * 4;
                int col = nb + 8 * ni + (L & 3) * 2;
                float bv0 = sbias[col], bv1 = sbias[col + 1];
                int row0 = mr + 16 * mi + (L >> 2);
#pragma unroll
                for (int rr = 0; rr < 2; ++rr) {
                    int row = row0 + rr * 8;
                    float* zp = g_zx + (size_t)(t0 + (row >> 4)) * 131072 +
                                bid * 1024 + (row & 15) * 64;
                    zp[(col & 15) * 4 + (col >> 4)] = d[rr * 2 + 0] + bv0;
                    zp[((col + 1) & 15) * 4 + ((col + 1) >> 4)] =
                        d[rr * 2 + 1] + bv1;
                }
            }
        }

        if ((nt & 31) == 31) {   // bound drift (keep x slabs L2-resident)
            __syncthreads();
            if (tid == 0) {
                unsigned a = atomicAdd(&g_count, 1u);
                if (((a + 1u) & (NCTA - 1u)) == 0u) g_gen = g_gen + 1u;
                ++epoch;
                while ((unsigned)(g_gen - gen0) < epoch) __nanosleep(64);
            }
            __syncthreads();
        }
    }
}

// ========================= PHASE 2: HMMA recurrence (R14, unchanged) ========
extern "C" __global__ void __launch_bounds__(NTHR, 1)
lstm_rec(const float* __restrict__ c0,
         const float* __restrict__ h0,
         const float* __restrict__ Wh,
         float* __restrict__ out,
         long long out_size) {
    extern __shared__ char sm[];
    const uint32_t smb = (uint32_t)__cvta_generic_to_shared(sm);
    float* red = (float*)(sm + RRED);
    __shared__ unsigned s_fbase;

    const int tid = threadIdx.x;
    const int bid = blockIdx.x;
    const int gd  = bid & 31, gb = bid >> 5;
    const int d0  = gd * 16;
    const int wid = tid >> 5;
    const int L   = tid & 31;

    if (tid == 0) s_fbase = ldflag(&g_flags[bid * 8]);
    fill_w_bf16(sm + RW_HI, sm + RW_LO, Wh, d0);

    const int nq = wid & 3;
    const int kq = wid >> 2;

    const uint32_t amr = (uint32_t)((L & 15) * 1040 + (L >> 4) * 16);
    const uint32_t boff =
        (uint32_t)((nq * 16 + (L & 7) + ((L >> 4) & 1) * 8) * 1040 +
                   ((L >> 3) & 1) * 16);
    const uint32_t a_hi = smb + RA_HI + amr + kq * 256;
    const uint32_t a_lo = smb + RA_LO + amr + kq * 256;
    const uint32_t b_hi = smb + RW_HI + boff + kq * 256;
    const uint32_t b_lo = smb + RW_LO + boff + kq * 256;

    const int eb   = tid >> 4;
    const int dloc = tid & 15;

    const int hr = tid >> 5;
    const int hc = tid & 31;

    float c_reg = 0.f;
    if (tid < 256) c_reg = c0[(gb * 16 + eb) * 512 + d0 + dloc];
    __syncthreads();
    const unsigned fbase = s_fbase;

    const float* zx_base = g_zx + (size_t)bid * 1024;

    float4 zx = make_float4(0.f, 0.f, 0.f, 0.f);
    if (tid < 256) zx = __ldcg((const float4*)(zx_base + (size_t)tid * 4));

    for (int t = 0; t < TS; ++t) {
        if (t > 0 && tid < 32) {
            unsigned tgt = fbase + (unsigned)t;
            const unsigned* fp = &g_flags[(gb * 32 + tid) * 8];
            while ((int)(ldflag_acq(fp) - tgt) < 0) __nanosleep(32);
        }
        __syncthreads();

        if (t == 0) {
            const float* hp = h0 + (size_t)(gb * 16 + hr) * 512 + hc * 16;
            float4 f0 = *(const float4*)(hp + 0);
            float4 f1 = *(const float4*)(hp + 4);
            float4 f2 = *(const float4*)(hp + 8);
            float4 f3 = *(const float4*)(hp + 12);
            uint4 hu0, hu1, lu0, lu1;
            hu0.x = pack_hi_lo(f0.x, f0.y, lu0.x);
            hu0.y = pack_hi_lo(f0.z, f0.w, lu0.y);
            hu0.z = pack_hi_lo(f1.x, f1.y, lu0.z);
            hu0.w = pack_hi_lo(f1.z, f1.w, lu0.w);
            hu1.x = pack_hi_lo(f2.x, f2.y, lu1.x);
            hu1.y = pack_hi_lo(f2.z, f2.w, lu1.y);
            hu1.z = pack_hi_lo(f3.x, f3.y, lu1.z);
            hu1.w = pack_hi_lo(f3.z, f3.w, lu1.w);
            char* ah = sm + RA_HI + hr * 1040 + hc * 32;
            char* al = sm + RA_LO + hr * 1040 + hc * 32;
            *(uint4*)(ah) = hu0;
            *(uint4*)(ah + 16) = hu1;
            *(uint4*)(al) = lu0;
            *(uint4*)(al + 16) = lu1;
        } else {
            const __nv_bfloat16* hhi = g_hb[t & 1][0] +
                                       (size_t)(gb * 16 + hr) * 512;
            const __nv_bfloat16* hlo = g_hb[t & 1][1] +
                                       (size_t)(gb * 16 + hr) * 512;
            char* ah = sm + RA_HI + hr * 1040;
            char* al = sm + RA_LO + hr * 1040;
            cpa16(ah + hc * 16,        (const char*)hhi + hc * 16);
            cpa16(ah + (hc + 32) * 16, (const char*)hhi + (hc + 32) * 16);
            cpa16(al + hc * 16,        (const char*)hlo + hc * 16);
            cpa16(al + (hc + 32) * 16, (const char*)hlo + (hc + 32) * 16);
            CPA_COMMIT();
            CPA_WAIT0();
        }
        __syncthreads();

        float4 zx_next = make_float4(0.f, 0.f, 0.f, 0.f);
        if (tid < 256 && t + 1 < TS)
            zx_next = __ldcg((const float4*)(zx_base +
                        (size_t)(t + 1) * (NCTA * 1024) + (size_t)tid * 4));

        float acc[8];
#pragma unroll
        for (int i = 0; i < 8; ++i) acc[i] = 0.f;
#pragma unroll
        for (int ks = 0; ks < 8; ++ks) {
            const uint32_t ko = (uint32_t)ks * 32;
            uint32_t ah[4], al[4], bh[4], bl[4];
            ldm4(ah, a_hi + ko);
            ldm4(bh, b_hi + ko);
            mma16816(acc + 0, ah, bh + 0);
            mma16816(acc + 4, ah, bh + 2);
            ldm4(bl, b_lo + ko);
            mma16816(acc + 0, ah, bl + 0);
            mma16816(acc + 4, ah, bl + 2);
            ldm4(al, a_lo + ko);
            mma16816(acc + 0, al, bh + 0);
            mma16816(acc + 4, al, bh + 2);
        }

        {
            int c0i = nq * 16 + (L & 3) * 2;
            int row0 = L >> 2;
#pragma unroll
            for (int rr = 0; rr < 2; ++rr) {
                int row = row0 + rr * 8;
                float* rp = &red[(kq * 16 + row) * 68];
                *(float2*)(rp + c0i)     = make_float2(acc[rr * 2 + 0],
                                                       acc[rr * 2 + 1]);
                *(float2*)(rp + c0i + 8) = make_float2(acc[4 + rr * 2 + 0],
                                                       acc[4 + rr * 2 + 1]);
            }
        }
        __syncthreads();

        float hh = 0.f, cc = 0.f;
        if (tid < 256) {
            float zi = zx.x, zf = zx.y, zg = zx.z, zo = zx.w;
#pragma unroll
            for (int k4 = 0; k4 < 4; ++k4) {
                const float* r = &red[(k4 * 16 + eb) * 68 + dloc];
                zi += r[0];
                zf += r[16];
                zg += r[32];
                zo += r[48];
            }
            cc = sigf(zf) * c_reg + sigf(zi) * tanhfast(zg);
            hh = sigf(zo) * tanhfast(cc);
            c_reg = cc;
            __nv_bfloat16 hhi = __float2bfloat16(hh);
            __nv_bfloat16 hlo = __float2bfloat16(hh - __bfloat162float(hhi));
            size_t hoff = (size_t)(gb * 16 + eb) * 512 + d0 + dloc;
            st_b16(&g_hb[(t + 1) & 1][0][hoff], hhi);
            st_b16(&g_hb[(t + 1) & 1][1][hoff], hlo);
        }
        __syncthreads();

        if (tid == 0) {
            asm volatile("fence.acq_rel.gpu;" ::: "memory");
            __stcg(&g_flags[bid * 8], fbase + (unsigned)(t + 1));
        }

        if (tid < 256) {
            int d = d0 + dloc;
            int bgl = gb * 16 + eb;
            out[(size_t)t * 32768 + bgl * 512 + d] = hh;
            if (t == TS - 1 && out_size >= 33554432LL + 65536LL) {
                out[33554432 + bgl * 512 + d] = cc;
                out[33554432 + 32768 + bgl * 512 + d] = hh;
            }
        }
        zx = zx_next;
    }
}

extern "C" void kernel_launch(void* const* d_in, const int* in_sizes, int n_in,
                              void* d_out, int out_size) {
    const float* x  = (const float*)d_in[0];
    const float* c0 = (const float*)d_in[1];
    const float* h0 = (const float*)d_in[2];
    const float* Wi = (const float*)d_in[3];
    const float* Wh = (const float*)d_in[4];
    const float* b  = (const float*)d_in[5];

    cudaFuncSetAttribute(lstm_zx,
                         cudaFuncAttributeMaxDynamicSharedMemorySize, ZX_SMEM);
    cudaFuncSetAttribute(lstm_rec,
                         cudaFuncAttributeMaxDynamicSharedMemorySize, REC_SMEM);

    lstm_cvt<<<NCTA, NTHR>>>(x);
    lstm_zx<<<NCTA, NTHR, ZX_SMEM>>>(Wi, b);
    lstm_rec<<<NCTA, NTHR, REC_SMEM>>>(c0, h0, Wh, (float*)d_out,
                                       (long long)out_size);
}